// round 16
// baseline (speedup 1.0000x reference)
#include <cuda_runtime.h>
#include <cuda_bf16.h>

// ---------------------------------------------------------------------------
// AIMNet2 interaction module — fused per-atom formulation.
//
//   radial[i]   = Σ_{p∈i} f_p * A[j_p]
//   s[i,c,:]    = Σ_{p∈i} (f_p u[p,c]) * A[j_p]
//   vec[i,c,:]  = W @ s[i,c,:] + deg(i)*b
//   out[i]      = [ sqrt(Σ_c vec² + 1e-12), radial ]
//
// Pipeline: hist -> parallel 2-phase scan -> scatter (sorted meta
//   {f, f*ux, f*uy, f*uz} + j) -> fused kernel:
//   gather = unrolled groups of 8 pairs, all loads issued up front (MLP=16);
//   matvec = 2 atoms batched per W pass, W pre-packed in smem as g-pair
//   ulls, packed fma.rn.f32x2 (fma-pipe-bound).
// ---------------------------------------------------------------------------

#define FDIM 128
#define MAX_ATOMS 20480
#define MAX_PAIRS 393216
#define CHUNK 2
#define MAIN_BLOCKS 296
#define WARPS_PER_BLOCK 8
#define MAIN_THREADS (WARPS_PER_BLOCK * 32)
#define MAIN_WARPS (MAIN_BLOCKS * WARPS_PER_BLOCK)

typedef unsigned long long ull;

__device__ int g_count[MAX_ATOMS + 1];
__device__ int g_start[MAX_ATOMS + 1];
__device__ int g_cursor[MAX_ATOMS + 1];
__device__ int g_btot[64];
__device__ int g_j[MAX_PAIRS];
__device__ __align__(16) float4 g_meta[MAX_PAIRS];   // {f, f*ux, f*uy, f*uz}

__device__ __forceinline__ ull dup2(float v) {
    ull d; asm("mov.b64 %0, {%1, %1};" : "=l"(d) : "f"(v)); return d;
}
__device__ __forceinline__ ull pack2(float lo, float hi) {
    ull d; asm("mov.b64 %0, {%1, %2};" : "=l"(d) : "f"(lo), "f"(hi)); return d;
}
__device__ __forceinline__ void unpack2(ull v, float& lo, float& hi) {
    asm("mov.b64 {%0, %1}, %2;" : "=f"(lo), "=f"(hi) : "l"(v));
}
#define FMA2(acc, a, b) \
    asm("fma.rn.f32x2 %0, %1, %2, %0;" : "+l"(acc) : "l"(a), "l"(b))

// ---------------------------------------------------------------------------
__global__ void zero_counts_kernel(int n_atoms) {
    int i = blockIdx.x * blockDim.x + threadIdx.x;
    if (i <= n_atoms) g_count[i] = 0;
}

__global__ void hist_kernel(const int* __restrict__ pl, int n_pairs) {
    int p = blockIdx.x * blockDim.x + threadIdx.x;
    if (p < n_pairs) atomicAdd(&g_count[pl[p]], 1);
}

// Phase A: per-block tile scan -> local-exclusive g_start, block total g_btot.
__global__ void scanA_kernel(int n) {
    __shared__ int wsum[32];
    const int tid = threadIdx.x;
    const int lane = tid & 31;
    const int w = tid >> 5;
    const int idx = blockIdx.x * 1024 + tid;
    int v = (idx < n) ? g_count[idx] : 0;
    int incl = v;
    #pragma unroll
    for (int off = 1; off < 32; off <<= 1) {
        int t = __shfl_up_sync(0xffffffffu, incl, off);
        if (lane >= off) incl += t;
    }
    if (lane == 31) wsum[w] = incl;
    __syncthreads();
    if (w == 0) {
        int s = wsum[lane];
        int i2 = s;
        #pragma unroll
        for (int off = 1; off < 32; off <<= 1) {
            int t = __shfl_up_sync(0xffffffffu, i2, off);
            if (lane >= off) i2 += t;
        }
        wsum[lane] = i2 - s;
    }
    __syncthreads();
    int excl = wsum[w] + incl - v;
    if (idx < n) g_start[idx] = excl;
    if (tid == 1023) g_btot[blockIdx.x] = wsum[w] + incl;
}

// Phase B/C fused: warp-scan of block totals, add offset, fill g_cursor.
__global__ void scanC_kernel(int n, int nb) {
    __shared__ int s_off;
    const int tid = threadIdx.x;
    if (tid < 32) {
        int t = (tid < nb) ? g_btot[tid] : 0;
        int incl = t;
        #pragma unroll
        for (int off = 1; off < 32; off <<= 1) {
            int x = __shfl_up_sync(0xffffffffu, incl, off);
            if (tid >= off) incl += x;
        }
        int excl = incl - t;
        int my = __shfl_sync(0xffffffffu, excl, blockIdx.x);
        if (tid == 0) s_off = my;
    }
    __syncthreads();
    const int idx = blockIdx.x * 1024 + tid;
    if (idx < n) {
        int v = g_start[idx] + s_off;
        g_start[idx] = v;
        g_cursor[idx] = v;
    }
}

// Scatter: sort pairs by idx_i, precomputing meta {f, f*ux, f*uy, f*uz}.
__global__ void scatter_kernel(const int* __restrict__ pl,
                               const float* __restrict__ fc,
                               const float* __restrict__ rij,
                               int n_pairs) {
    int p = blockIdx.x * blockDim.x + threadIdx.x;
    if (p < n_pairs) {
        int i = pl[p];
        int j = pl[n_pairs + p];
        float f = __ldg(fc + p);
        float rx = __ldg(rij + 3 * p + 0);
        float ry = __ldg(rij + 3 * p + 1);
        float rz = __ldg(rij + 3 * p + 2);
        float inv = f * rsqrtf(rx * rx + ry * ry + rz * rz);
        int pos = atomicAdd(&g_cursor[i], 1);
        g_meta[pos] = make_float4(f, rx * inv, ry * inv, rz * inv);
        g_j[pos] = j;
    }
}

// ---------------------------------------------------------------------------
// Gather group of up to 8 pairs: issue all 16 loads, then 128 FMAs.
// ---------------------------------------------------------------------------
template<bool FULL>
__device__ __forceinline__ void gather_group(
    const float* __restrict__ A, int fbase, int base, int q0, int m, int jj,
    float4& racc, float4& sx, float4& sy, float4& sz)
{
    float4 av[8], mv[8];
    #pragma unroll
    for (int k = 0; k < 8; k++) {
        int qk = q0 + k;
        int kk = FULL ? qk : (qk < m ? qk : 0);
        int j = __shfl_sync(0xffffffffu, jj, kk);
        av[k] = *reinterpret_cast<const float4*>(A + (size_t)j * FDIM + fbase);
        mv[k] = g_meta[base + kk];
        if (!FULL && qk >= m) mv[k] = make_float4(0.f, 0.f, 0.f, 0.f);
    }
    #pragma unroll
    for (int k = 0; k < 8; k++) {
        float4 av_ = av[k], mm = mv[k];
        racc.x = fmaf(mm.x, av_.x, racc.x); racc.y = fmaf(mm.x, av_.y, racc.y);
        racc.z = fmaf(mm.x, av_.z, racc.z); racc.w = fmaf(mm.x, av_.w, racc.w);
        sx.x = fmaf(mm.y, av_.x, sx.x); sx.y = fmaf(mm.y, av_.y, sx.y);
        sx.z = fmaf(mm.y, av_.z, sx.z); sx.w = fmaf(mm.y, av_.w, sx.w);
        sy.x = fmaf(mm.z, av_.x, sy.x); sy.y = fmaf(mm.z, av_.y, sy.y);
        sy.z = fmaf(mm.z, av_.z, sy.z); sy.w = fmaf(mm.z, av_.w, sy.w);
        sz.x = fmaf(mm.w, av_.x, sz.x); sz.y = fmaf(mm.w, av_.y, sz.y);
        sz.z = fmaf(mm.w, av_.z, sz.z); sz.w = fmaf(mm.w, av_.w, sz.w);
    }
}

// ---------------------------------------------------------------------------
// Main fused kernel: warp processes CHUNK=2 atoms per grid-stride step.
// smem: WT2 [128 f][64 gpair] ull = {W[2gp,f], W[2gp+1,f]}  (64 KB)
//       S2  [8 warps][CHUNK][3][128] ull  (dup2-staged s)    (48 KB)
// ---------------------------------------------------------------------------
#define S2_ROW 128                             // ull per component row
#define S2_PER_ATOM (3 * S2_ROW)
#define S2_PER_WARP (CHUNK * S2_PER_ATOM)
#define SMEM_MAIN (FDIM * 64 * 8 + WARPS_PER_BLOCK * S2_PER_WARP * 8) // 114,688

__global__ void __launch_bounds__(MAIN_THREADS, 2)
main_kernel(const float* __restrict__ A,
            const float* __restrict__ W,
            const float* __restrict__ bvec,
            float*       __restrict__ out,
            int n_atoms)
{
    extern __shared__ char smem_raw[];
    ull* WT2 = reinterpret_cast<ull*>(smem_raw);                 // [128][64]
    ull* S2  = reinterpret_cast<ull*>(smem_raw + FDIM * 64 * 8); // per-warp s

    const int tid  = threadIdx.x;
    const int wid  = tid >> 5;
    const int lane = tid & 31;

    // Stage W as packed g-pairs: WT2[f][gp] = {W[2gp][f], W[2gp+1][f]}
    for (int idx = tid; idx < FDIM * 64; idx += MAIN_THREADS) {
        int f = idx >> 6, gp = idx & 63;
        WT2[f * 64 + gp] = pack2(__ldg(W + (2 * gp) * FDIM + f),
                                 __ldg(W + (2 * gp + 1) * FDIM + f));
    }
    __syncthreads();

    ull* s2w = S2 + wid * S2_PER_WARP;
    const int fbase = 4 * lane;
    const int n_chunks = (n_atoms + CHUNK - 1) / CHUNK;

    for (int ch = blockIdx.x * WARPS_PER_BLOCK + wid; ch < n_chunks;
         ch += MAIN_WARPS) {
        const int abase = ch * CHUNK;
        float degs[CHUNK];

        __syncwarp();   // previous chunk's matvec reads of s2w are done

        // ================= gather: CHUNK atoms, high-MLP ===================
        #pragma unroll
        for (int a = 0; a < CHUNK; a++) {
            const int atom = abase + a;
            float4 racc = make_float4(0.f, 0.f, 0.f, 0.f);
            float4 sx = racc, sy = racc, sz = racc;
            degs[a] = 0.f;

            if (atom < n_atoms) {
                const int s0 = g_start[atom];
                const int s1 = g_start[atom + 1];
                degs[a] = (float)(s1 - s0);

                for (int base = s0; base < s1; base += 32) {
                    int m = s1 - base; if (m > 32) m = 32;
                    int jj = (lane < m) ? g_j[base + lane] : 0;
                    int q0 = 0;
                    for (; q0 + 8 <= m; q0 += 8)
                        gather_group<true>(A, fbase, base, q0, m, jj,
                                           racc, sx, sy, sz);
                    if (q0 < m)
                        gather_group<false>(A, fbase, base, q0, m, jj,
                                            racc, sx, sy, sz);
                }
                *reinterpret_cast<float4*>(
                    out + (size_t)atom * (2 * FDIM) + FDIM + fbase) = racc;
            }
            // stage s duplicated ({v,v}); zeros for OOB atoms
            ull* sa = s2w + a * S2_PER_ATOM;
            sa[0 * S2_ROW + fbase + 0] = dup2(sx.x);
            sa[0 * S2_ROW + fbase + 1] = dup2(sx.y);
            sa[0 * S2_ROW + fbase + 2] = dup2(sx.z);
            sa[0 * S2_ROW + fbase + 3] = dup2(sx.w);
            sa[1 * S2_ROW + fbase + 0] = dup2(sy.x);
            sa[1 * S2_ROW + fbase + 1] = dup2(sy.y);
            sa[1 * S2_ROW + fbase + 2] = dup2(sy.z);
            sa[1 * S2_ROW + fbase + 3] = dup2(sy.w);
            sa[2 * S2_ROW + fbase + 0] = dup2(sz.x);
            sa[2 * S2_ROW + fbase + 1] = dup2(sz.y);
            sa[2 * S2_ROW + fbase + 2] = dup2(sz.z);
            sa[2 * S2_ROW + fbase + 3] = dup2(sz.w);
        }
        __syncwarp();

        // ================= matvec: 2 atoms per W pass, packed f32x2 ========
        // acc layout: [atom][component c][g-half h] -> acc[a*6 + c*2 + h]
        ull acc[CHUNK * 6];
        #pragma unroll
        for (int k = 0; k < CHUNK * 6; k++) acc[k] = 0;

        const ull* wrow = WT2 + 2 * lane;   // lane owns g = 4l..4l+3 (2 gpairs)

        #pragma unroll 4
        for (int f = 0; f < FDIM; f++) {
            ulonglong2 wp = *reinterpret_cast<const ulonglong2*>(wrow + f * 64);
            #pragma unroll
            for (int a = 0; a < CHUNK; a++) {
                const ull* sa = s2w + a * S2_PER_ATOM + f;
                ull sb0 = sa[0 * S2_ROW];
                ull sb1 = sa[1 * S2_ROW];
                ull sb2 = sa[2 * S2_ROW];
                FMA2(acc[a*6+0], sb0, wp.x); FMA2(acc[a*6+1], sb0, wp.y);
                FMA2(acc[a*6+2], sb1, wp.x); FMA2(acc[a*6+3], sb1, wp.y);
                FMA2(acc[a*6+4], sb2, wp.x); FMA2(acc[a*6+5], sb2, wp.y);
            }
        }

        // ================= epilogue: bias + norm + store ===================
        float4 bb = __ldg(reinterpret_cast<const float4*>(bvec + fbase));
        float bbv[4] = {bb.x, bb.y, bb.z, bb.w};
        #pragma unroll
        for (int a = 0; a < CHUNK; a++) {
            const int atom = abase + a;
            if (atom >= n_atoms) break;
            float tx[4], ty[4], tz[4];
            unpack2(acc[a*6+0], tx[0], tx[1]); unpack2(acc[a*6+1], tx[2], tx[3]);
            unpack2(acc[a*6+2], ty[0], ty[1]); unpack2(acc[a*6+3], ty[2], ty[3]);
            unpack2(acc[a*6+4], tz[0], tz[1]); unpack2(acc[a*6+5], tz[2], tz[3]);
            float4 nrm;
            float* nv = &nrm.x;
            #pragma unroll
            for (int k = 0; k < 4; k++) {
                float db = degs[a] * bbv[k];
                float x = tx[k] + db;
                float y = ty[k] + db;
                float z = tz[k] + db;
                nv[k] = sqrtf(x * x + y * y + z * z + 1e-12f);
            }
            *reinterpret_cast<float4*>(out + (size_t)atom * (2 * FDIM) + fbase) = nrm;
        }
    }
}

// ---------------------------------------------------------------------------
extern "C" void kernel_launch(void* const* d_in, const int* in_sizes, int n_in,
                              void* d_out, int out_size) {
    const float* A   = (const float*)d_in[0];
    const int*   pl  = (const int*)d_in[1];
    const float* fc  = (const float*)d_in[2];
    const float* rij = (const float*)d_in[3];
    const float* W   = (const float*)d_in[4];
    const float* b   = (const float*)d_in[5];
    float* out = (float*)d_out;

    int n_atoms = in_sizes[0] / FDIM;
    int n_pairs = in_sizes[2];

    static int smem_set = 0;
    if (!smem_set) {
        cudaFuncSetAttribute(main_kernel,
                             cudaFuncAttributeMaxDynamicSharedMemorySize, SMEM_MAIN);
        smem_set = 1;
    }

    int pb = (n_pairs + 255) / 256;
    int n_scan = n_atoms + 1;
    int nb = (n_scan + 1023) / 1024;

    zero_counts_kernel<<<(n_scan + 255) / 256, 256>>>(n_atoms);
    hist_kernel<<<pb, 256>>>(pl, n_pairs);
    scanA_kernel<<<nb, 1024>>>(n_scan);
    scanC_kernel<<<nb, 1024>>>(n_scan, nb);
    scatter_kernel<<<pb, 256>>>(pl, fc, rij, n_pairs);
    main_kernel<<<MAIN_BLOCKS, MAIN_THREADS, SMEM_MAIN>>>(A, W, b, out, n_atoms);
}

// round 17
// speedup vs baseline: 1.3855x; 1.3855x over previous
#include <cuda_runtime.h>
#include <cuda_bf16.h>

// ---------------------------------------------------------------------------
// AIMNet2 interaction module — fused per-atom formulation.
//
//   radial[i]   = Σ_{p∈i} f_p * A[j_p]
//   s[i,c,:]    = Σ_{p∈i} (f_p u[p,c]) * A[j_p]
//   vec[i,c,:]  = W @ s[i,c,:] + deg(i)*b
//   out[i]      = [ sqrt(Σ_c vec² + 1e-12), radial ]
//
// Pipeline: hist (x4-batched, zeroes scan status) -> decoupled-lookback scan
//   (fills g_start/g_cursor, re-zeroes g_count for next replay) -> scatter
//   (x4-batched, sorted meta {f,f*ux,f*uy,f*uz} + j) -> fused main kernel:
//   gather = unrolled groups of 8 pairs, all loads up front (MLP=16);
//   matvec = packed fma.rn.f32x2 with W pre-packed in smem as g-pair ulls.
// ---------------------------------------------------------------------------

#define FDIM 128
#define S2_S 132
#define MAX_ATOMS 20480
#define MAX_PAIRS 393216
#define MAIN_BLOCKS 296
#define WARPS_PER_BLOCK 8
#define MAIN_THREADS (WARPS_PER_BLOCK * 32)
#define MAIN_WARPS (MAIN_BLOCKS * WARPS_PER_BLOCK)

typedef unsigned long long ull;

__device__ int g_count[MAX_ATOMS + 1];     // static zero-init covers 1st call
__device__ int g_start[MAX_ATOMS + 1];
__device__ int g_cursor[MAX_ATOMS + 1];
__device__ int g_status[32];               // lookback: 0 none, 1 agg, 2 prefix
__device__ int g_agg[32];
__device__ int g_pref[32];
__device__ int g_j[MAX_PAIRS];
__device__ __align__(16) float4 g_meta[MAX_PAIRS];   // {f, f*ux, f*uy, f*uz}

__device__ __forceinline__ ull dup2(float v) {
    ull d; asm("mov.b64 %0, {%1, %1};" : "=l"(d) : "f"(v)); return d;
}
__device__ __forceinline__ ull pack2(float lo, float hi) {
    ull d; asm("mov.b64 %0, {%1, %2};" : "=l"(d) : "f"(lo), "f"(hi)); return d;
}
__device__ __forceinline__ void unpack2(ull v, float& lo, float& hi) {
    asm("mov.b64 {%0, %1}, %2;" : "=f"(lo), "=f"(hi) : "l"(v));
}
#define FMA2(acc, a, b) \
    asm("fma.rn.f32x2 %0, %1, %2, %0;" : "+l"(acc) : "l"(a), "l"(b))

// ---------------------------------------------------------------------------
// Histogram, 4 pairs per thread; block 0 also zeroes the scan status flags.
// ---------------------------------------------------------------------------
__global__ void hist_kernel(const int* __restrict__ pl, int n_pairs) {
    if (blockIdx.x == 0 && threadIdx.x < 32) g_status[threadIdx.x] = 0;
    int t = blockIdx.x * blockDim.x + threadIdx.x;
    int p0 = 4 * t;
    if (p0 + 3 < n_pairs) {
        int4 i4 = *reinterpret_cast<const int4*>(pl + p0);
        atomicAdd(&g_count[i4.x], 1);
        atomicAdd(&g_count[i4.y], 1);
        atomicAdd(&g_count[i4.z], 1);
        atomicAdd(&g_count[i4.w], 1);
    } else {
        for (int p = p0; p < n_pairs; p++) atomicAdd(&g_count[pl[p]], 1);
    }
}

// ---------------------------------------------------------------------------
// Single-pass decoupled-lookback scan over g_count[0..n) -> exclusive
// g_start/g_cursor; re-zeroes g_count for the next graph replay.
// ---------------------------------------------------------------------------
__global__ void scan_kernel(int n) {
    __shared__ int wsum[32];
    __shared__ int s_carry;
    const int tid = threadIdx.x;
    const int lane = tid & 31;
    const int w = tid >> 5;
    const int b = blockIdx.x;
    const int idx = b * 1024 + tid;

    int v = (idx < n) ? g_count[idx] : 0;
    int incl = v;
    #pragma unroll
    for (int off = 1; off < 32; off <<= 1) {
        int t = __shfl_up_sync(0xffffffffu, incl, off);
        if (lane >= off) incl += t;
    }
    if (lane == 31) wsum[w] = incl;
    __syncthreads();
    if (w == 0) {
        int s = wsum[lane];
        int i2 = s;
        #pragma unroll
        for (int off = 1; off < 32; off <<= 1) {
            int t = __shfl_up_sync(0xffffffffu, i2, off);
            if (lane >= off) i2 += t;
        }
        wsum[lane] = i2 - s;      // exclusive warp offset
    }
    __syncthreads();
    int excl = wsum[w] + incl - v;            // tile-local exclusive
    int total = wsum[31] + __shfl_sync(0xffffffffu, incl, 31, 32);
    // recompute tile total robustly from thread 1023's inclusive value:
    __shared__ int s_total;
    if (tid == 1023) s_total = excl + v;
    __syncthreads();
    total = s_total;

    if (tid == 0) {
        g_agg[b] = total;
        __threadfence();
        atomicExch(&g_status[b], 1);
        // decoupled lookback
        int running = 0;
        for (int t = b - 1; t >= 0; t--) {
            int st;
            do { st = atomicAdd(&g_status[t], 0); } while (st == 0);
            if (st == 2) { running += atomicAdd(&g_pref[t], 0); break; }
            running += atomicAdd(&g_agg[t], 0);
        }
        g_pref[b] = running + total;
        __threadfence();
        atomicExch(&g_status[b], 2);
        s_carry = running;
    }
    __syncthreads();
    int carry = s_carry;
    if (idx < n) {
        int val = excl + carry;
        g_start[idx] = val;
        g_cursor[idx] = val;
        g_count[idx] = 0;         // ready for next replay (1st call: static 0)
    }
}

// ---------------------------------------------------------------------------
// Scatter, 4 pairs per thread: sort by idx_i, precompute meta.
// ---------------------------------------------------------------------------
__global__ void scatter_kernel(const int* __restrict__ pl,
                               const float* __restrict__ fc,
                               const float* __restrict__ rij,
                               int n_pairs) {
    int t = blockIdx.x * blockDim.x + threadIdx.x;
    int p0 = 4 * t;
    if (p0 + 3 < n_pairs) {
        int4 i4 = *reinterpret_cast<const int4*>(pl + p0);
        int4 j4 = *reinterpret_cast<const int4*>(pl + n_pairs + p0);
        float4 f4 = *reinterpret_cast<const float4*>(fc + p0);
        float4 ra = *reinterpret_cast<const float4*>(rij + 3 * p0);
        float4 rb = *reinterpret_cast<const float4*>(rij + 3 * p0 + 4);
        float4 rc = *reinterpret_cast<const float4*>(rij + 3 * p0 + 8);
        float rx[4] = {ra.x, ra.w, rb.z, rc.y};
        float ry[4] = {ra.y, rb.x, rb.w, rc.z};
        float rz[4] = {ra.z, rb.y, rc.x, rc.w};
        int   ii[4] = {i4.x, i4.y, i4.z, i4.w};
        int   jj[4] = {j4.x, j4.y, j4.z, j4.w};
        float ff[4] = {f4.x, f4.y, f4.z, f4.w};
        #pragma unroll
        for (int k = 0; k < 4; k++) {
            float inv = ff[k] * rsqrtf(rx[k] * rx[k] + ry[k] * ry[k] + rz[k] * rz[k]);
            int pos = atomicAdd(&g_cursor[ii[k]], 1);
            g_meta[pos] = make_float4(ff[k], rx[k] * inv, ry[k] * inv, rz[k] * inv);
            g_j[pos] = jj[k];
        }
    } else {
        for (int p = p0; p < n_pairs; p++) {
            int i = pl[p];
            int j = pl[n_pairs + p];
            float f = __ldg(fc + p);
            float rx = __ldg(rij + 3 * p + 0);
            float ry = __ldg(rij + 3 * p + 1);
            float rz = __ldg(rij + 3 * p + 2);
            float inv = f * rsqrtf(rx * rx + ry * ry + rz * rz);
            int pos = atomicAdd(&g_cursor[i], 1);
            g_meta[pos] = make_float4(f, rx * inv, ry * inv, rz * inv);
            g_j[pos] = j;
        }
    }
}

// ---------------------------------------------------------------------------
// Gather group of up to 8 pairs: issue all 16 loads, then 128 FMAs.
// ---------------------------------------------------------------------------
template<bool FULL>
__device__ __forceinline__ void gather_group(
    const float* __restrict__ A, int fbase, int base, int q0, int m, int jj,
    float4& racc, float4& sx, float4& sy, float4& sz)
{
    float4 av[8], mv[8];
    #pragma unroll
    for (int k = 0; k < 8; k++) {
        int qk = q0 + k;
        int kk = FULL ? qk : (qk < m ? qk : 0);
        int j = __shfl_sync(0xffffffffu, jj, kk);
        av[k] = *reinterpret_cast<const float4*>(A + (size_t)j * FDIM + fbase);
        mv[k] = g_meta[base + kk];
        if (!FULL && qk >= m) mv[k] = make_float4(0.f, 0.f, 0.f, 0.f);
    }
    #pragma unroll
    for (int k = 0; k < 8; k++) {
        float4 av_ = av[k], mm = mv[k];
        racc.x = fmaf(mm.x, av_.x, racc.x); racc.y = fmaf(mm.x, av_.y, racc.y);
        racc.z = fmaf(mm.x, av_.z, racc.z); racc.w = fmaf(mm.x, av_.w, racc.w);
        sx.x = fmaf(mm.y, av_.x, sx.x); sx.y = fmaf(mm.y, av_.y, sx.y);
        sx.z = fmaf(mm.y, av_.z, sx.z); sx.w = fmaf(mm.y, av_.w, sx.w);
        sy.x = fmaf(mm.z, av_.x, sy.x); sy.y = fmaf(mm.z, av_.y, sy.y);
        sy.z = fmaf(mm.z, av_.z, sy.z); sy.w = fmaf(mm.z, av_.w, sy.w);
        sz.x = fmaf(mm.w, av_.x, sz.x); sz.y = fmaf(mm.w, av_.y, sz.y);
        sz.z = fmaf(mm.w, av_.z, sz.z); sz.w = fmaf(mm.w, av_.w, sz.w);
    }
}

// ---------------------------------------------------------------------------
// Main fused kernel (R15 skeleton: warp = 1 atom per grid-stride step).
// smem: WT2 [128 f][64 gpair] ull = {W[2gp,f],W[2gp+1,f]}  (64 KB)
//       S2  [8 warps][3][S2_S] ull (dup2-staged s)          (25.3 KB)
// Total 90,880 B -> 2 blocks/SM.
// ---------------------------------------------------------------------------
#define SMEM_MAIN (FDIM * 64 * 8 + WARPS_PER_BLOCK * 3 * S2_S * 8)

__global__ void __launch_bounds__(MAIN_THREADS, 2)
main_kernel(const float* __restrict__ A,
            const float* __restrict__ W,
            const float* __restrict__ bvec,
            float*       __restrict__ out,
            int n_atoms)
{
    extern __shared__ char smem_raw[];
    ull* WT2 = reinterpret_cast<ull*>(smem_raw);                 // [128][64]
    ull* S2  = reinterpret_cast<ull*>(smem_raw + FDIM * 64 * 8);

    const int tid  = threadIdx.x;
    const int wid  = tid >> 5;
    const int lane = tid & 31;

    // Stage W pre-packed: WT2[f][gp] = {W[2gp][f], W[2gp+1][f]}
    for (int idx = tid; idx < FDIM * 64; idx += MAIN_THREADS) {
        int f = idx >> 6, gp = idx & 63;
        WT2[f * 64 + gp] = pack2(__ldg(W + (2 * gp) * FDIM + f),
                                 __ldg(W + (2 * gp + 1) * FDIM + f));
    }
    __syncthreads();

    ull* s2w = S2 + wid * 3 * S2_S;
    const int fbase = 4 * lane;

    for (int atom = blockIdx.x * WARPS_PER_BLOCK + wid; atom < n_atoms;
         atom += MAIN_WARPS) {
        const int s0 = g_start[atom];
        const int s1 = g_start[atom + 1];

        // ================= gather: grouped, high-MLP =======================
        float4 racc = make_float4(0.f, 0.f, 0.f, 0.f);
        float4 sx = racc, sy = racc, sz = racc;

        for (int base = s0; base < s1; base += 32) {
            int m = s1 - base; if (m > 32) m = 32;
            int jj = (lane < m) ? g_j[base + lane] : 0;
            int q0 = 0;
            for (; q0 + 8 <= m; q0 += 8)
                gather_group<true>(A, fbase, base, q0, m, jj, racc, sx, sy, sz);
            if (q0 < m)
                gather_group<false>(A, fbase, base, q0, m, jj, racc, sx, sy, sz);
        }

        // radial half of the output
        *reinterpret_cast<float4*>(
            out + (size_t)atom * (2 * FDIM) + FDIM + fbase) = racc;

        // ---- stage s duplicated ({v,v}) for packed broadcast reads ----
        __syncwarp();   // prior atom's matvec reads of s2w are done
        s2w[0 * S2_S + fbase + 0] = dup2(sx.x);
        s2w[0 * S2_S + fbase + 1] = dup2(sx.y);
        s2w[0 * S2_S + fbase + 2] = dup2(sx.z);
        s2w[0 * S2_S + fbase + 3] = dup2(sx.w);
        s2w[1 * S2_S + fbase + 0] = dup2(sy.x);
        s2w[1 * S2_S + fbase + 1] = dup2(sy.y);
        s2w[1 * S2_S + fbase + 2] = dup2(sy.z);
        s2w[1 * S2_S + fbase + 3] = dup2(sy.w);
        s2w[2 * S2_S + fbase + 0] = dup2(sz.x);
        s2w[2 * S2_S + fbase + 1] = dup2(sz.y);
        s2w[2 * S2_S + fbase + 2] = dup2(sz.z);
        s2w[2 * S2_S + fbase + 3] = dup2(sz.w);
        __syncwarp();

        // ================= matvec: packed f32x2, pre-packed W ==============
        ull a00 = 0, a01 = 0, a10 = 0, a11 = 0, a20 = 0, a21 = 0;
        const ull* wrow = WT2 + 2 * lane;   // lane owns g = 4l..4l+3

        #pragma unroll 8
        for (int f = 0; f < FDIM; f++) {
            ulonglong2 wp = *reinterpret_cast<const ulonglong2*>(wrow + f * 64);
            ull sb0 = s2w[0 * S2_S + f];
            ull sb1 = s2w[1 * S2_S + f];
            ull sb2 = s2w[2 * S2_S + f];
            FMA2(a00, sb0, wp.x); FMA2(a01, sb0, wp.y);
            FMA2(a10, sb1, wp.x); FMA2(a11, sb1, wp.y);
            FMA2(a20, sb2, wp.x); FMA2(a21, sb2, wp.y);
        }

        // ================= epilogue: bias + norm + store ===================
        float tx[4], ty[4], tz[4];
        unpack2(a00, tx[0], tx[1]); unpack2(a01, tx[2], tx[3]);
        unpack2(a10, ty[0], ty[1]); unpack2(a11, ty[2], ty[3]);
        unpack2(a20, tz[0], tz[1]); unpack2(a21, tz[2], tz[3]);

        float deg = (float)(s1 - s0);
        float4 bb = __ldg(reinterpret_cast<const float4*>(bvec + fbase));
        float bbv[4] = {bb.x, bb.y, bb.z, bb.w};

        float4 nrm;
        float* nv = &nrm.x;
        #pragma unroll
        for (int k = 0; k < 4; k++) {
            float db = deg * bbv[k];
            float x = tx[k] + db;
            float y = ty[k] + db;
            float z = tz[k] + db;
            nv[k] = sqrtf(x * x + y * y + z * z + 1e-12f);
        }
        *reinterpret_cast<float4*>(out + (size_t)atom * (2 * FDIM) + fbase) = nrm;
    }
}

// ---------------------------------------------------------------------------
extern "C" void kernel_launch(void* const* d_in, const int* in_sizes, int n_in,
                              void* d_out, int out_size) {
    const float* A   = (const float*)d_in[0];
    const int*   pl  = (const int*)d_in[1];
    const float* fc  = (const float*)d_in[2];
    const float* rij = (const float*)d_in[3];
    const float* W   = (const float*)d_in[4];
    const float* b   = (const float*)d_in[5];
    float* out = (float*)d_out;

    int n_atoms = in_sizes[0] / FDIM;
    int n_pairs = in_sizes[2];

    static int smem_set = 0;
    if (!smem_set) {
        cudaFuncSetAttribute(main_kernel,
                             cudaFuncAttributeMaxDynamicSharedMemorySize, SMEM_MAIN);
        smem_set = 1;
    }

    int n_scan = n_atoms + 1;
    int nb = (n_scan + 1023) / 1024;
    int qb = ((n_pairs + 3) / 4 + 255) / 256;

    hist_kernel<<<qb, 256>>>(pl, n_pairs);
    scan_kernel<<<nb, 1024>>>(n_scan);
    scatter_kernel<<<qb, 256>>>(pl, fc, rij, n_pairs);
    main_kernel<<<MAIN_BLOCKS, MAIN_THREADS, SMEM_MAIN>>>(A, W, b, out, n_atoms);
}